// round 3
// baseline (speedup 1.0000x reference)
#include <cuda_runtime.h>

#define BB 4
#define RR 64
#define FF 1024
#define DD 128
#define FT 64          // k2 f-tile width
#define NFT (FF/FT)    // 16 f-tiles

// ---------------- device scratch (static; no allocations) ----------------
__device__ float g_fproj[BB*FF*DD];          // frontier @ W1f            (2 MB)
__device__ float g_rproj[BB*RR*DD];          // robot @ W1r + b1
__device__ float g_wd[DD];                   // column sums of W1d
__device__ float g_escore[BB*RR*FF];         // exp(scores)               (1 MB)
__device__ float g_sums_part[NFT*BB*RR];     // per-ftile partial softmax sums
__device__ float g_msg_part[NFT*BB*RR*DD];   // per-ftile partial messages (2 MB)

// ---------------- kernel 1: projections -----------------------------------
// 512 threads. 32-row x 128-col output tiles.
// blocks 0..127  : f_proj  (b = blk>>5, ftile32 = blk&31)
// blocks 128..135: r_proj + b1 (b = (blk-128)>>1, rhalf = (blk-128)&1)
// block  136     : w_d column sums
#define K1_SMEM ((DD*DD + DD*34) * 4)

__global__ __launch_bounds__(512)
void k1_proj(const float* __restrict__ robot,
             const float* __restrict__ frontier,
             const float* __restrict__ W1,
             const float* __restrict__ b1) {
    extern __shared__ float sm[];
    float* w_s = sm;               // 128 x 128
    float* x_s = sm + DD*DD;       // x transposed [k][row], stride 34 (32 rows + pad)
    const int t   = threadIdx.x;
    const int blk = blockIdx.x;

    if (blk >= 136) {
        if (t < DD) {
            float s = 0.f;
            #pragma unroll 8
            for (int k = 0; k < DD; k++) s += W1[(2*DD + k)*DD + t];
            g_wd[t] = s;
        }
        return;
    }

    const float* W;
    const float* X;
    float* O;
    bool add_b1;
    if (blk < 128) {
        int b = blk >> 5, ft = blk & 31;
        W = W1 + DD*DD;                              // W1f rows
        X = frontier + (size_t)(b*FF + ft*32)*DD;
        O = g_fproj  + (size_t)(b*FF + ft*32)*DD;
        add_b1 = false;
    } else {
        int idx = blk - 128;
        int b = idx >> 1, rh = idx & 1;
        W = W1;                                      // W1r rows
        X = robot   + (size_t)(b*RR + rh*32)*DD;
        O = g_rproj + (size_t)(b*RR + rh*32)*DD;
        add_b1 = true;
    }

    for (int i = t; i < DD*DD; i += 512) w_s[i] = W[i];
    for (int i = t; i < 32*DD; i += 512) {
        int r = i >> 7, k = i & 127;
        x_s[k*34 + r] = X[i];
    }
    __syncthreads();

    const int cg = t & 31, rg = t >> 5;
    const int c0 = cg*4, r0 = rg*2;
    float acc[2][4];
    #pragma unroll
    for (int i = 0; i < 2; i++)
        #pragma unroll
        for (int j = 0; j < 4; j++) acc[i][j] = 0.f;

    #pragma unroll 4
    for (int k = 0; k < DD; k++) {
        float2 x2 = *(const float2*)&x_s[k*34 + r0];
        float4 w4 = *(const float4*)&w_s[k*DD + c0];
        float xv[2] = {x2.x, x2.y};
        float wv[4] = {w4.x, w4.y, w4.z, w4.w};
        #pragma unroll
        for (int i = 0; i < 2; i++)
            #pragma unroll
            for (int j = 0; j < 4; j++)
                acc[i][j] = fmaf(xv[i], wv[j], acc[i][j]);
    }

    if (add_b1) {
        #pragma unroll
        for (int j = 0; j < 4; j++) {
            float bv = b1[c0 + j];
            #pragma unroll
            for (int i = 0; i < 2; i++) acc[i][j] += bv;
        }
    }

    #pragma unroll
    for (int i = 0; i < 2; i++)
        *(float4*)&O[(r0+i)*DD + c0] = make_float4(acc[i][0], acc[i][1], acc[i][2], acc[i][3]);
}

// ---------------- kernel 2: fused scores + exp + partial softmax + partial messages
// 512 threads. grid = 128: b = x>>5, ftile = (x>>1)&15, rhalf = x&1 (32 robots/block)
#define K2_SMEM_FLOATS (DD*33 + DD*68 + 32*65 + 64*132 + 64*33 + DD + DD + 32*16)
#define K2_SMEM (K2_SMEM_FLOATS * 4)

__global__ __launch_bounds__(512)
void k2_main(const float* __restrict__ frontier,
             const float* __restrict__ geo,
             const float* __restrict__ W2,
             const float* __restrict__ b2) {
    extern __shared__ float sm[];
    float* rp_s  = sm;                   // [d][r]  128 x 33
    float* fp_s  = rp_s  + DD*33;        // [d][f]  128 x 68
    float* geo_s = fp_s  + DD*68;        // [r][f]   32 x 65
    float* fr_s  = geo_s + 32*65;        // [f][d]   64 x 132
    float* e_s   = fr_s  + 64*132;       // [f][r]   64 x 33
    float* wd_s  = e_s   + 64*33;        // 128
    float* w2_s  = wd_s  + DD;           // 128
    float* ps_s  = w2_s  + DD;           // 32 x 16 partial sums

    const int t = threadIdx.x;
    const int x = blockIdx.x;
    const int b     = x >> 5;
    const int ftile = (x >> 1) & 15;
    const int rbase = (x & 1) * 32;

    const float* RP = g_rproj + (size_t)(b*RR + rbase)*DD;
    for (int i = t; i < 32*DD; i += 512) { int r = i >> 7, d = i & 127; rp_s[d*33 + r] = RP[i]; }
    const float* FP = g_fproj + (size_t)(b*FF + ftile*FT)*DD;
    for (int i = t; i < FT*DD; i += 512) { int f = i >> 7, d = i & 127; fp_s[d*68 + f] = FP[i]; }
    const float* FR = frontier + (size_t)(b*FF + ftile*FT)*DD;
    for (int i = t; i < FT*DD; i += 512) { int f = i >> 7, d = i & 127; fr_s[f*132 + d] = FR[i]; }
    const float* G = geo + (size_t)(b*RR + rbase)*FF + ftile*FT;
    for (int i = t; i < 32*FT; i += 512) { int r = i >> 6, f = i & 63; geo_s[r*65 + f] = G[r*FF + f]; }
    if (t < DD) { wd_s[t] = g_wd[t]; w2_s[t] = W2[t]; }
    __syncthreads();

    // ---- phase A: scores (1r x 4f per thread over 32r x 64f) ----
    const int fx = t & 15, r = t >> 4;
    const int f0 = fx*4;

    float gg[4];
    #pragma unroll
    for (int j = 0; j < 4; j++) gg[j] = geo_s[r*65 + f0 + j];

    float acc[4] = {0.f, 0.f, 0.f, 0.f};

    #pragma unroll 4
    for (int d = 0; d < DD; d++) {
        float rpv = rp_s[d*33 + r];
        float4 fp4 = *(const float4*)&fp_s[d*68 + f0];
        float wdv = wd_s[d], w2v = w2_s[d];
        float fpv[4] = {fp4.x, fp4.y, fp4.z, fp4.w};
        #pragma unroll
        for (int j = 0; j < 4; j++) {
            float v = rpv + fpv[j];
            v = fmaf(gg[j], wdv, v);
            v = fmaxf(v, 0.f);
            acc[j] = fmaf(v, w2v, acc[j]);
        }
    }

    const float b2v = b2[0];
    float p = 0.f;
    #pragma unroll
    for (int j = 0; j < 4; j++) {
        float s = fmaxf(acc[j] + b2v, 0.f);
        float e = __expf(s);                // scores >= 0 and small: exact softmax w/o max-sub
        acc[j] = e;
        p += e;
        e_s[(f0+j)*33 + r] = e;
    }
    ps_s[r*16 + fx] = p;

    float* EO = g_escore + (size_t)(b*RR + rbase)*FF + ftile*FT;
    *(float4*)&EO[r*FF + f0] = make_float4(acc[0], acc[1], acc[2], acc[3]);
    __syncthreads();

    if (t < 32) {
        float s = 0.f;
        #pragma unroll
        for (int q = 0; q < 16; q++) s += ps_s[t*16 + q];
        g_sums_part[ftile*(BB*RR) + b*RR + rbase + t] = s;
    }

    // ---- phase B: partial messages (1r x 8d per thread over 32r x 128d) ----
    const int dg = t & 15, r2 = t >> 4;
    const int d0 = dg*8;
    float m[8];
    #pragma unroll
    for (int j = 0; j < 8; j++) m[j] = 0.f;

    #pragma unroll 4
    for (int f = 0; f < FT; f++) {
        float ev = e_s[f*33 + r2];
        float4 fA = *(const float4*)&fr_s[f*132 + d0];
        float4 fB = *(const float4*)&fr_s[f*132 + d0 + 4];
        float fv[8] = {fA.x, fA.y, fA.z, fA.w, fB.x, fB.y, fB.z, fB.w};
        #pragma unroll
        for (int j = 0; j < 8; j++)
            m[j] = fmaf(ev, fv[j], m[j]);
    }

    float* MO = g_msg_part + (size_t)(ftile*(BB*RR) + b*RR + rbase)*DD;
    *(float4*)&MO[r2*DD + d0]     = make_float4(m[0], m[1], m[2], m[3]);
    *(float4*)&MO[r2*DD + d0 + 4] = make_float4(m[4], m[5], m[6], m[7]);
}

// ---------------- kernel 3: normalize + outputs ----------------------------
// grid = 64 (4 robots per block), 128 threads. Wn re-read 64x instead of 256x.
__global__ __launch_bounds__(128)
void k3_out(const float* __restrict__ robot,
            const float* __restrict__ Wn,
            const float* __restrict__ bn,
            float* __restrict__ out) {
    __shared__ float comb[4][2*DD];
    __shared__ float sp[4][16];
    __shared__ float invs[4];
    const int br0 = blockIdx.x * 4;
    const int t   = threadIdx.x;

    if (t < 64) {
        int j = t >> 4, p = t & 15;
        sp[j][p] = g_sums_part[p*(BB*RR) + br0 + j];
    }
    __syncthreads();
    if (t < 4) {
        float s = 0.f;
        #pragma unroll
        for (int q = 0; q < 16; q++) s += sp[t][q];
        invs[t] = 1.0f / s;
    }
    __syncthreads();

    #pragma unroll
    for (int j = 0; j < 4; j++) {
        const int br = br0 + j;
        float mm = 0.f;
        #pragma unroll
        for (int p = 0; p < NFT; p++) mm += g_msg_part[(size_t)(p*(BB*RR) + br)*DD + t];
        comb[j][DD + t] = mm * invs[j];
        comb[j][t]      = robot[(size_t)br*DD + t];

        const float* E  = g_escore + (size_t)br*FF;
        float*       ew = out + (size_t)BB*RR*DD + (size_t)br*FF;
        #pragma unroll
        for (int k = 0; k < FF/DD; k++) ew[k*DD + t] = E[k*DD + t] * invs[j];
    }
    __syncthreads();

    float acc[4];
    const float bv = bn[t];
    #pragma unroll
    for (int j = 0; j < 4; j++) acc[j] = bv;

    #pragma unroll 4
    for (int k = 0; k < 2*DD; k++) {
        float w = Wn[k*DD + t];
        #pragma unroll
        for (int j = 0; j < 4; j++)
            acc[j] = fmaf(comb[j][k], w, acc[j]);
    }
    #pragma unroll
    for (int j = 0; j < 4; j++)
        out[(size_t)(br0 + j)*DD + t] = fmaxf(acc[j], 0.f);
}

// ---------------- launch ----------------------------------------------------
extern "C" void kernel_launch(void* const* d_in, const int* in_sizes, int n_in,
                              void* d_out, int out_size) {
    const float* robot    = (const float*)d_in[0];
    const float* frontier = (const float*)d_in[1];
    const float* geo      = (const float*)d_in[2];
    const float* W1       = (const float*)d_in[3];
    const float* b1       = (const float*)d_in[4];
    const float* W2       = (const float*)d_in[5];
    const float* b2       = (const float*)d_in[6];
    const float* Wn       = (const float*)d_in[7];
    const float* bn       = (const float*)d_in[8];
    float* out = (float*)d_out;

    cudaFuncSetAttribute(k1_proj, cudaFuncAttributeMaxDynamicSharedMemorySize, K1_SMEM);
    cudaFuncSetAttribute(k2_main, cudaFuncAttributeMaxDynamicSharedMemorySize, K2_SMEM);

    k1_proj<<<137, 512, K1_SMEM>>>(robot, frontier, W1, b1);
    k2_main<<<128, 512, K2_SMEM>>>(frontier, geo, W2, b2);
    k3_out<<<64, 128>>>(robot, Wn, bn, out);
}

// round 5
// speedup vs baseline: 1.2146x; 1.2146x over previous
#include <cuda_runtime.h>

#define BB 4
#define RR 64
#define FF 1024
#define DD 128
#define FT 64          // k2 f-tile width
#define NFT (FF/FT)    // 16 f-tiles

// ---------------- device scratch (static; no allocations) ----------------
__device__ float g_fproj[BB*FF*DD];          // frontier @ W1f            (2 MB)
__device__ float g_rproj[BB*RR*DD];          // robot @ W1r + b1
__device__ float g_wd[DD];                   // column sums of W1d
__device__ float g_escore[BB*RR*FF];         // exp(scores)               (1 MB)
__device__ float g_sums_part[NFT*BB*RR];     // per-ftile partial softmax sums
__device__ float g_msg_part[NFT*BB*RR*DD];   // per-ftile partial messages (2 MB)

// ---------------- kernel 1: projections -----------------------------------
// 256 threads, 32-row x 128-col tiles, 4r x 4c (16 accs) per thread.
// blocks 0..127  : f_proj  (b = blk>>5, ftile32 = blk&31)
// blocks 128..135: r_proj + b1
// block  136     : w_d column sums
#define K1_SMEM ((DD*DD + DD*36) * 4)

__global__ __launch_bounds__(256)
void k1_proj(const float* __restrict__ robot,
             const float* __restrict__ frontier,
             const float* __restrict__ W1,
             const float* __restrict__ b1) {
    extern __shared__ float sm[];
    float* w_s = sm;               // 128 x 128
    float* x_s = sm + DD*DD;       // x transposed [k][row], stride 36
    const int t   = threadIdx.x;
    const int blk = blockIdx.x;

    if (blk >= 136) {
        if (t < DD) {
            float s = 0.f;
            #pragma unroll 8
            for (int k = 0; k < DD; k++) s += W1[(2*DD + k)*DD + t];
            g_wd[t] = s;
        }
        return;
    }

    const float* W;
    const float* X;
    float* O;
    bool add_b1;
    if (blk < 128) {
        int b = blk >> 5, ft = blk & 31;
        W = W1 + DD*DD;                              // W1f rows
        X = frontier + (size_t)(b*FF + ft*32)*DD;
        O = g_fproj  + (size_t)(b*FF + ft*32)*DD;
        add_b1 = false;
    } else {
        int idx = blk - 128;
        int b = idx >> 1, rh = idx & 1;
        W = W1;                                      // W1r rows
        X = robot   + (size_t)(b*RR + rh*32)*DD;
        O = g_rproj + (size_t)(b*RR + rh*32)*DD;
        add_b1 = true;
    }

    for (int i = t; i < DD*DD; i += 256) w_s[i] = W[i];
    for (int i = t; i < 32*DD; i += 256) {
        int r = i >> 7, k = i & 127;
        x_s[k*36 + r] = X[i];
    }
    __syncthreads();

    const int cg = t & 31, rg = t >> 5;
    const int c0 = cg*4, r0 = rg*4;
    float acc[4][4];
    #pragma unroll
    for (int i = 0; i < 4; i++)
        #pragma unroll
        for (int j = 0; j < 4; j++) acc[i][j] = 0.f;

    #pragma unroll 8
    for (int k = 0; k < DD; k++) {
        float4 x4 = *(const float4*)&x_s[k*36 + r0];   // broadcast within warp
        float4 w4 = *(const float4*)&w_s[k*DD + c0];
        float xv[4] = {x4.x, x4.y, x4.z, x4.w};
        float wv[4] = {w4.x, w4.y, w4.z, w4.w};
        #pragma unroll
        for (int i = 0; i < 4; i++)
            #pragma unroll
            for (int j = 0; j < 4; j++)
                acc[i][j] = fmaf(xv[i], wv[j], acc[i][j]);
    }

    if (add_b1) {
        #pragma unroll
        for (int j = 0; j < 4; j++) {
            float bv = b1[c0 + j];
            #pragma unroll
            for (int i = 0; i < 4; i++) acc[i][j] += bv;
        }
    }

    #pragma unroll
    for (int i = 0; i < 4; i++)
        *(float4*)&O[(r0+i)*DD + c0] = make_float4(acc[i][0], acc[i][1], acc[i][2], acc[i][3]);
}

// ---------------- kernel 2: fused scores + exp + partial softmax + partial messages
// 512 threads; phase A splits the d-reduction across two 256-thread halves
// (relu is applied per-d, so partial d-sums combine exactly).
// grid = 128: b = x>>5, ftile = (x>>1)&15, rhalf = x&1 (32 robots/block)
#define K2_SMEM_FLOATS (DD*36 + DD*68 + 32*65 + 64*132 + 64*36 + 2*DD + 32*16 + 256*8)
#define K2_SMEM (K2_SMEM_FLOATS * 4)

__global__ __launch_bounds__(512)
void k2_main(const float* __restrict__ frontier,
             const float* __restrict__ geo,
             const float* __restrict__ W2,
             const float* __restrict__ b2) {
    extern __shared__ float sm[];
    float*  rp_s  = sm;                    // [d][r]  128 x 36
    float*  fp_s  = rp_s  + DD*36;         // [d][f]  128 x 68
    float*  geo_s = fp_s  + DD*68;         // [r][f]   32 x 65
    float*  fr_s  = geo_s + 32*65;         // [f][d]   64 x 132
    float*  e_s   = fr_s  + 64*132;        // [f][r]   64 x 36
    float2* wz_s  = (float2*)(e_s + 64*36);// 128 x {wd, w2}
    float*  ps_s  = e_s + 64*36 + 2*DD;    // 32 x 16 partial sums
    float*  pa_s  = ps_s + 32*16;          // 256 x 8 partial accs (d-split combine)

    const int t = threadIdx.x;
    const int x = blockIdx.x;
    const int b     = x >> 5;
    const int ftile = (x >> 1) & 15;
    const int rbase = (x & 1) * 32;

    const float* RP = g_rproj + (size_t)(b*RR + rbase)*DD;
    for (int i = t; i < 32*DD; i += 512) { int r = i >> 7, d = i & 127; rp_s[d*36 + r] = RP[i]; }
    const float* FP = g_fproj + (size_t)(b*FF + ftile*FT)*DD;
    for (int i = t; i < FT*DD; i += 512) { int f = i >> 7, d = i & 127; fp_s[d*68 + f] = FP[i]; }
    const float* FR = frontier + (size_t)(b*FF + ftile*FT)*DD;
    for (int i = t; i < FT*DD; i += 512) { int f = i >> 7, d = i & 127; fr_s[f*132 + d] = FR[i]; }
    const float* G = geo + (size_t)(b*RR + rbase)*FF + ftile*FT;
    for (int i = t; i < 32*FT; i += 512) { int r = i >> 6, f = i & 63; geo_s[r*65 + f] = G[r*FF + f]; }
    if (t < DD) wz_s[t] = make_float2(g_wd[t], W2[t]);
    __syncthreads();

    // ---- phase A: scores, 2r x 4f per thread, d split across halves ----
    const int half = t >> 8;        // 0 or 1
    const int tt   = t & 255;
    const int fx = tt & 15, rx = tt >> 4;
    const int f0 = fx*4,  r0 = rx*2;
    const int dbeg = half * 64;

    float gg[2][4];
    #pragma unroll
    for (int i = 0; i < 2; i++)
        #pragma unroll
        for (int j = 0; j < 4; j++)
            gg[i][j] = geo_s[(r0+i)*65 + f0 + j];

    float acc[2][4];
    #pragma unroll
    for (int i = 0; i < 2; i++)
        #pragma unroll
        for (int j = 0; j < 4; j++) acc[i][j] = 0.f;

    #pragma unroll 8
    for (int dd = 0; dd < 64; dd++) {
        const int d = dbeg + dd;
        float2 rp2 = *(const float2*)&rp_s[d*36 + r0];
        float4 fp4 = *(const float4*)&fp_s[d*68 + f0];
        float2 wz  = wz_s[d];
        float rpv[2] = {rp2.x, rp2.y};
        float fpv[4] = {fp4.x, fp4.y, fp4.z, fp4.w};
        #pragma unroll
        for (int i = 0; i < 2; i++)
            #pragma unroll
            for (int j = 0; j < 4; j++) {
                float v = rpv[i] + fpv[j];
                v = fmaf(gg[i][j], wz.x, v);
                v = fmaxf(v, 0.f);
                acc[i][j] = fmaf(v, wz.y, acc[i][j]);
            }
    }

    if (half) {
        #pragma unroll
        for (int i = 0; i < 2; i++)
            #pragma unroll
            for (int j = 0; j < 4; j++)
                pa_s[tt*8 + i*4 + j] = acc[i][j];
    }
    __syncthreads();

    if (!half) {
        const float b2v = b2[0];
        float p0 = 0.f, p1 = 0.f;
        #pragma unroll
        for (int i = 0; i < 2; i++)
            #pragma unroll
            for (int j = 0; j < 4; j++) {
                float s = fmaxf(acc[i][j] + pa_s[tt*8 + i*4 + j] + b2v, 0.f);
                float e = __expf(s);       // scores >= 0, small: exact softmax w/o max-sub
                acc[i][j] = e;
                if (i == 0) p0 += e; else p1 += e;
                e_s[(f0+j)*36 + r0 + i] = e;
            }
        ps_s[(r0+0)*16 + fx] = p0;
        ps_s[(r0+1)*16 + fx] = p1;

        float* EO = g_escore + (size_t)(b*RR + rbase)*FF + ftile*FT;
        *(float4*)&EO[(r0+0)*FF + f0] = make_float4(acc[0][0], acc[0][1], acc[0][2], acc[0][3]);
        *(float4*)&EO[(r0+1)*FF + f0] = make_float4(acc[1][0], acc[1][1], acc[1][2], acc[1][3]);
    }
    __syncthreads();

    if (t < 32) {
        float s = 0.f;
        #pragma unroll
        for (int q = 0; q < 16; q++) s += ps_s[t*16 + q];
        g_sums_part[ftile*(BB*RR) + b*RR + rbase + t] = s;
    }

    // ---- phase B: partial messages, 1r x 8d per thread across 512 threads ----
    const int dg = t & 15, r2 = t >> 4;   // r2 in 0..31
    const int d0 = dg*8;
    float m[8];
    #pragma unroll
    for (int j = 0; j < 8; j++) m[j] = 0.f;

    #pragma unroll 8
    for (int f = 0; f < FT; f++) {
        float ev = e_s[f*36 + r2];
        float4 fA = *(const float4*)&fr_s[f*132 + d0];
        float4 fB = *(const float4*)&fr_s[f*132 + d0 + 4];
        float fv[8] = {fA.x, fA.y, fA.z, fA.w, fB.x, fB.y, fB.z, fB.w};
        #pragma unroll
        for (int j = 0; j < 8; j++)
            m[j] = fmaf(ev, fv[j], m[j]);
    }

    float* MO = g_msg_part + (size_t)(ftile*(BB*RR) + b*RR + rbase)*DD;
    *(float4*)&MO[r2*DD + d0]     = make_float4(m[0], m[1], m[2], m[3]);
    *(float4*)&MO[r2*DD + d0 + 4] = make_float4(m[4], m[5], m[6], m[7]);
}

// ---------------- kernel 3: normalize + outputs (R2 proven version) --------
// grid = 256 (one per (b,r)), 128 threads
__global__ __launch_bounds__(128)
void k3_out(const float* __restrict__ robot,
            const float* __restrict__ Wn,
            const float* __restrict__ bn,
            float* __restrict__ out) {
    __shared__ float comb[2*DD];
    const int br = blockIdx.x;
    const int t  = threadIdx.x;

    float s = 0.f;
    #pragma unroll
    for (int p = 0; p < NFT; p++) s += g_sums_part[p*(BB*RR) + br];
    const float inv = 1.0f / s;

    float mm = 0.f;
    #pragma unroll
    for (int p = 0; p < NFT; p++) mm += g_msg_part[(size_t)(p*(BB*RR) + br)*DD + t];
    comb[DD + t] = mm * inv;
    comb[t]      = robot[(size_t)br*DD + t];

    const float* E  = g_escore + (size_t)br*FF;
    float*       ew = out + (size_t)BB*RR*DD + (size_t)br*FF;
    #pragma unroll
    for (int k = 0; k < FF/DD; k++) ew[k*DD + t] = E[k*DD + t] * inv;
    __syncthreads();

    float acc = bn[t];
    #pragma unroll 8
    for (int k = 0; k < 2*DD; k++) acc = fmaf(comb[k], Wn[k*DD + t], acc);
    out[(size_t)br*DD + t] = fmaxf(acc, 0.f);
}

// ---------------- launch ----------------------------------------------------
extern "C" void kernel_launch(void* const* d_in, const int* in_sizes, int n_in,
                              void* d_out, int out_size) {
    const float* robot    = (const float*)d_in[0];
    const float* frontier = (const float*)d_in[1];
    const float* geo      = (const float*)d_in[2];
    const float* W1       = (const float*)d_in[3];
    const float* b1       = (const float*)d_in[4];
    const float* W2       = (const float*)d_in[5];
    const float* b2       = (const float*)d_in[6];
    const float* Wn       = (const float*)d_in[7];
    const float* bn       = (const float*)d_in[8];
    float* out = (float*)d_out;

    cudaFuncSetAttribute(k1_proj, cudaFuncAttributeMaxDynamicSharedMemorySize, K1_SMEM);
    cudaFuncSetAttribute(k2_main, cudaFuncAttributeMaxDynamicSharedMemorySize, K2_SMEM);

    k1_proj<<<137, 256, K1_SMEM>>>(robot, frontier, W1, b1);
    k2_main<<<128, 512, K2_SMEM>>>(frontier, geo, W2, b2);
    k3_out<<<256, 128>>>(robot, Wn, bn, out);
}

// round 7
// speedup vs baseline: 1.2727x; 1.0478x over previous
#include <cuda_runtime.h>

#define BB 4
#define RR 64
#define FF 1024
#define DD 128
#define DK 130         // DD + 2 pad rows for prefetch-distance-2 reads
#define FT 64          // k2 f-tile width
#define FTP 66         // FT + 2 pad rows
#define NFT (FF/FT)    // 16 f-tiles

// ---------------- device scratch (static; no allocations) ----------------
__device__ float g_fproj[BB*FF*DD];
__device__ float g_rproj[BB*RR*DD];
__device__ float g_wd[DD];
__device__ float g_escore[BB*RR*FF];
__device__ float g_sums_part[NFT*BB*RR];
__device__ float g_msg_part[NFT*BB*RR*DD];

// ---------------- kernel 1: projections -----------------------------------
// 256 threads, 32-row x 128-col tiles, 4r x 4c (16 accs) per thread,
// explicit distance-2 smem->register prefetch pipeline.
#define K1_SMEM ((DK*DD + DK*36) * 4)

__global__ __launch_bounds__(256)
void k1_proj(const float* __restrict__ robot,
             const float* __restrict__ frontier,
             const float* __restrict__ W1,
             const float* __restrict__ b1) {
    extern __shared__ float sm[];
    float* w_s = sm;               // DK x 128 (rows 0..127 valid)
    float* x_s = sm + DK*DD;       // DK x 36  (x transposed [k][row])
    const int t   = threadIdx.x;
    const int blk = blockIdx.x;

    if (blk >= 136) {
        if (t < DD) {
            float s = 0.f;
            #pragma unroll 8
            for (int k = 0; k < DD; k++) s += W1[(2*DD + k)*DD + t];
            g_wd[t] = s;
        }
        return;
    }

    const float* W;
    const float* X;
    float* O;
    bool add_b1;
    if (blk < 128) {
        int b = blk >> 5, ft = blk & 31;
        W = W1 + DD*DD;
        X = frontier + (size_t)(b*FF + ft*32)*DD;
        O = g_fproj  + (size_t)(b*FF + ft*32)*DD;
        add_b1 = false;
    } else {
        int idx = blk - 128;
        int b = idx >> 1, rh = idx & 1;
        W = W1;
        X = robot   + (size_t)(b*RR + rh*32)*DD;
        O = g_rproj + (size_t)(b*RR + rh*32)*DD;
        add_b1 = true;
    }

    for (int i = t; i < DD*DD; i += 256) w_s[i] = W[i];
    for (int i = t; i < 32*DD; i += 256) {
        int r = i >> 7, k = i & 127;
        x_s[k*36 + r] = X[i];
    }
    __syncthreads();

    const int cg = t & 31, rg = t >> 5;
    const int c0 = cg*4, r0 = rg*4;
    float acc[4][4];
    #pragma unroll
    for (int i = 0; i < 4; i++)
        #pragma unroll
        for (int j = 0; j < 4; j++) acc[i][j] = 0.f;

    #define X4(k) (*(const float4*)&x_s[(k)*36 + r0])
    #define W4(k) (*(const float4*)&w_s[(k)*DD + c0])

    float4 xa = X4(0), wa = W4(0);
    float4 xb = X4(1), wb = W4(1);

    #pragma unroll 4
    for (int k = 0; k < DD; k += 2) {
        float4 xc  = X4(k+2), wc  = W4(k+2);   // prefetch (pad rows: junk never consumed)
        float4 xd  = X4(k+3), wd4 = W4(k+3);
        {
            float xv[4] = {xa.x, xa.y, xa.z, xa.w};
            float wv[4] = {wa.x, wa.y, wa.z, wa.w};
            #pragma unroll
            for (int i = 0; i < 4; i++)
                #pragma unroll
                for (int j = 0; j < 4; j++)
                    acc[i][j] = fmaf(xv[i], wv[j], acc[i][j]);
        }
        {
            float xv[4] = {xb.x, xb.y, xb.z, xb.w};
            float wv[4] = {wb.x, wb.y, wb.z, wb.w};
            #pragma unroll
            for (int i = 0; i < 4; i++)
                #pragma unroll
                for (int j = 0; j < 4; j++)
                    acc[i][j] = fmaf(xv[i], wv[j], acc[i][j]);
        }
        xa = xc; wa = wc; xb = xd; wb = wd4;
    }
    #undef X4
    #undef W4

    if (add_b1) {
        #pragma unroll
        for (int j = 0; j < 4; j++) {
            float bv = b1[c0 + j];
            #pragma unroll
            for (int i = 0; i < 4; i++) acc[i][j] += bv;
        }
    }

    #pragma unroll
    for (int i = 0; i < 4; i++)
        *(float4*)&O[(r0+i)*DD + c0] = make_float4(acc[i][0], acc[i][1], acc[i][2], acc[i][3]);
}

// ---------------- kernel 2: fused scores + exp + softmax partials + message partials
// 512 threads; phase A d-split across halves; explicit prefetch pipelines.
#define K2_SMEM_FLOATS (DK*36 + DK*68 + 32*65 + FTP*132 + FTP*36 + 2*DK + 32*16 + 256*8)
#define K2_SMEM (K2_SMEM_FLOATS * 4)

__global__ __launch_bounds__(512)
void k2_main(const float* __restrict__ frontier,
             const float* __restrict__ geo,
             const float* __restrict__ W2,
             const float* __restrict__ b2) {
    extern __shared__ float sm[];
    float*  rp_s  = sm;                      // [d][r]  DK x 36
    float*  fp_s  = rp_s  + DK*36;           // [d][f]  DK x 68
    float*  geo_s = fp_s  + DK*68;           // [r][f]  32 x 65
    float*  fr_s  = geo_s + 32*65;           // [f][d]  FTP x 132
    float*  e_s   = fr_s  + FTP*132;         // [f][r]  FTP x 36
    float2* wz_s  = (float2*)(e_s + FTP*36); // DK x {wd, w2}
    float*  ps_s  = e_s + FTP*36 + 2*DK;     // 32 x 16
    float*  pa_s  = ps_s + 32*16;            // 256 x 8

    const int t = threadIdx.x;
    const int x = blockIdx.x;
    const int b     = x >> 5;
    const int ftile = (x >> 1) & 15;
    const int rbase = (x & 1) * 32;

    const float* RP = g_rproj + (size_t)(b*RR + rbase)*DD;
    for (int i = t; i < 32*DD; i += 512) { int r = i >> 7, d = i & 127; rp_s[d*36 + r] = RP[i]; }
    const float* FP = g_fproj + (size_t)(b*FF + ftile*FT)*DD;
    for (int i = t; i < FT*DD; i += 512) { int f = i >> 7, d = i & 127; fp_s[d*68 + f] = FP[i]; }
    const float* FR = frontier + (size_t)(b*FF + ftile*FT)*DD;
    for (int i = t; i < FT*DD; i += 512) { int f = i >> 7, d = i & 127; fr_s[f*132 + d] = FR[i]; }
    const float* G = geo + (size_t)(b*RR + rbase)*FF + ftile*FT;
    for (int i = t; i < 32*FT; i += 512) { int r = i >> 6, f = i & 63; geo_s[r*65 + f] = G[r*FF + f]; }
    if (t < DD) wz_s[t] = make_float2(g_wd[t], W2[t]);
    __syncthreads();

    // ---- phase A: scores, 2r x 4f per thread, d split across halves ----
    const int half = t >> 8;
    const int tt   = t & 255;
    const int fx = tt & 15, rx = tt >> 4;
    const int f0 = fx*4,  r0 = rx*2;
    const int dbeg = half * 64;

    float gg[2][4];
    #pragma unroll
    for (int i = 0; i < 2; i++)
        #pragma unroll
        for (int j = 0; j < 4; j++)
            gg[i][j] = geo_s[(r0+i)*65 + f0 + j];

    float acc[2][4];
    #pragma unroll
    for (int i = 0; i < 2; i++)
        #pragma unroll
        for (int j = 0; j < 4; j++) acc[i][j] = 0.f;

    #define RP2(d) (*(const float2*)&rp_s[(d)*36 + r0])
    #define FP4(d) (*(const float4*)&fp_s[(d)*68 + f0])

    float2 ra = RP2(dbeg),   rb = RP2(dbeg+1);
    float4 fa = FP4(dbeg),   fb = FP4(dbeg+1);
    float2 za = wz_s[dbeg],  zb = wz_s[dbeg+1];

    #pragma unroll 4
    for (int dd = 0; dd < 64; dd += 2) {
        const int d2 = dbeg + dd + 2, d3 = dbeg + dd + 3;
        float2 rc = RP2(d2), rd = RP2(d3);     // prefetch
        float4 fc = FP4(d2), fd = FP4(d3);
        float2 zc = wz_s[d2], zd = wz_s[d3];
        {
            float rpv[2] = {ra.x, ra.y};
            float fpv[4] = {fa.x, fa.y, fa.z, fa.w};
            #pragma unroll
            for (int i = 0; i < 2; i++)
                #pragma unroll
                for (int j = 0; j < 4; j++) {
                    float v = rpv[i] + fpv[j];
                    v = fmaf(gg[i][j], za.x, v);
                    v = fmaxf(v, 0.f);
                    acc[i][j] = fmaf(v, za.y, acc[i][j]);
                }
        }
        {
            float rpv[2] = {rb.x, rb.y};
            float fpv[4] = {fb.x, fb.y, fb.z, fb.w};
            #pragma unroll
            for (int i = 0; i < 2; i++)
                #pragma unroll
                for (int j = 0; j < 4; j++) {
                    float v = rpv[i] + fpv[j];
                    v = fmaf(gg[i][j], zb.x, v);
                    v = fmaxf(v, 0.f);
                    acc[i][j] = fmaf(v, zb.y, acc[i][j]);
                }
        }
        ra = rc; fa = fc; za = zc;
        rb = rd; fb = fd; zb = zd;
    }
    #undef RP2
    #undef FP4

    if (half) {
        #pragma unroll
        for (int i = 0; i < 2; i++)
            #pragma unroll
            for (int j = 0; j < 4; j++)
                pa_s[tt*8 + i*4 + j] = acc[i][j];
    }
    __syncthreads();

    if (!half) {
        const float b2v = b2[0];
        float p0 = 0.f, p1 = 0.f;
        #pragma unroll
        for (int i = 0; i < 2; i++)
            #pragma unroll
            for (int j = 0; j < 4; j++) {
                float s = fmaxf(acc[i][j] + pa_s[tt*8 + i*4 + j] + b2v, 0.f);
                float e = __expf(s);       // scores >= 0, small: exact softmax w/o max-sub
                acc[i][j] = e;
                if (i == 0) p0 += e; else p1 += e;
                e_s[(f0+j)*36 + r0 + i] = e;
            }
        ps_s[(r0+0)*16 + fx] = p0;
        ps_s[(r0+1)*16 + fx] = p1;

        float* EO = g_escore + (size_t)(b*RR + rbase)*FF + ftile*FT;
        *(float4*)&EO[(r0+0)*FF + f0] = make_float4(acc[0][0], acc[0][1], acc[0][2], acc[0][3]);
        *(float4*)&EO[(r0+1)*FF + f0] = make_float4(acc[1][0], acc[1][1], acc[1][2], acc[1][3]);
    }
    __syncthreads();

    if (t < 32) {
        float s = 0.f;
        #pragma unroll
        for (int q = 0; q < 16; q++) s += ps_s[t*16 + q];
        g_sums_part[ftile*(BB*RR) + b*RR + rbase + t] = s;
    }

    // ---- phase B: partial messages, 1r x 8d per thread, prefetch pipeline ----
    const int dg = t & 15, r2 = t >> 4;
    const int d0 = dg*8;
    float m[8];
    #pragma unroll
    for (int j = 0; j < 8; j++) m[j] = 0.f;

    #define EV(f)  (e_s[(f)*36 + r2])
    #define FRA(f) (*(const float4*)&fr_s[(f)*132 + d0])
    #define FRB(f) (*(const float4*)&fr_s[(f)*132 + d0 + 4])

    float  ea = EV(0),  eb = EV(1);
    float4 Aa = FRA(0), Ba = FRB(0);
    float4 Ab = FRA(1), Bb = FRB(1);

    #pragma unroll 4
    for (int f = 0; f < FT; f += 2) {
        float  ec = EV(f+2),  ed = EV(f+3);    // prefetch
        float4 Ac = FRA(f+2), Bc = FRB(f+2);
        float4 Ad = FRA(f+3), Bd = FRB(f+3);
        {
            float fv[8] = {Aa.x, Aa.y, Aa.z, Aa.w, Ba.x, Ba.y, Ba.z, Ba.w};
            #pragma unroll
            for (int j = 0; j < 8; j++) m[j] = fmaf(ea, fv[j], m[j]);
        }
        {
            float fv[8] = {Ab.x, Ab.y, Ab.z, Ab.w, Bb.x, Bb.y, Bb.z, Bb.w};
            #pragma unroll
            for (int j = 0; j < 8; j++) m[j] = fmaf(eb, fv[j], m[j]);
        }
        ea = ec; Aa = Ac; Ba = Bc;
        eb = ed; Ab = Ad; Bb = Bd;
    }
    #undef EV
    #undef FRA
    #undef FRB

    float* MO = g_msg_part + (size_t)(ftile*(BB*RR) + b*RR + rbase)*DD;
    *(float4*)&MO[r2*DD + d0]     = make_float4(m[0], m[1], m[2], m[3]);
    *(float4*)&MO[r2*DD + d0 + 4] = make_float4(m[4], m[5], m[6], m[7]);
}

// ---------------- kernel 3: normalize + outputs ----------------------------
__global__ __launch_bounds__(128)
void k3_out(const float* __restrict__ robot,
            const float* __restrict__ Wn,
            const float* __restrict__ bn,
            float* __restrict__ out) {
    __shared__ float comb[2*DD];
    const int br = blockIdx.x;
    const int t  = threadIdx.x;

    float s = 0.f;
    #pragma unroll
    for (int p = 0; p < NFT; p++) s += g_sums_part[p*(BB*RR) + br];
    const float inv = 1.0f / s;

    float mm = 0.f;
    #pragma unroll
    for (int p = 0; p < NFT; p++) mm += g_msg_part[(size_t)(p*(BB*RR) + br)*DD + t];
    comb[DD + t] = mm * inv;
    comb[t]      = robot[(size_t)br*DD + t];

    const float* E  = g_escore + (size_t)br*FF;
    float*       ew = out + (size_t)BB*RR*DD + (size_t)br*FF;
    #pragma unroll
    for (int k = 0; k < FF/DD; k++) ew[k*DD + t] = E[k*DD + t] * inv;
    __syncthreads();

    float acc = bn[t];
    #pragma unroll 8
    for (int k = 0; k < 2*DD; k++) acc = fmaf(comb[k], Wn[k*DD + t], acc);
    out[(size_t)br*DD + t] = fmaxf(acc, 0.f);
}

// ---------------- launch ----------------------------------------------------
extern "C" void kernel_launch(void* const* d_in, const int* in_sizes, int n_in,
                              void* d_out, int out_size) {
    const float* robot    = (const float*)d_in[0];
    const float* frontier = (const float*)d_in[1];
    const float* geo      = (const float*)d_in[2];
    const float* W1       = (const float*)d_in[3];
    const float* b1       = (const float*)d_in[4];
    const float* W2       = (const float*)d_in[5];
    const float* b2       = (const float*)d_in[6];
    const float* Wn       = (const float*)d_in[7];
    const float* bn       = (const float*)d_in[8];
    float* out = (float*)d_out;

    cudaFuncSetAttribute(k1_proj, cudaFuncAttributeMaxDynamicSharedMemorySize, K1_SMEM);
    cudaFuncSetAttribute(k2_main, cudaFuncAttributeMaxDynamicSharedMemorySize, K2_SMEM);

    k1_proj<<<137, 256, K1_SMEM>>>(robot, frontier, W1, b1);
    k2_main<<<128, 512, K2_SMEM>>>(frontier, geo, W2, b2);
    k3_out<<<256, 128>>>(robot, Wn, bn, out);
}